// round 15
// baseline (speedup 1.0000x reference)
#include <cuda_runtime.h>
#include <cuda_bf16.h>
#include <cuda_fp16.h>
#include <cstdint>

// ============================================================================
// RecurrentDecoder: 128-step GRU (B=1024, H=1024) + Linear(1024->256).
// Decoder folded into recurrence: one GEMM/step  G = h @ Wp^T (+biasp),
//   Wp[4096,1024] gate-interleaved rows 4j+g, g in {r, z, i_n, h_n}.
//   r=sig(d0), z=sig(d1), n=tanh(d2 + r*d3), h' = n + z*(h - n)
// All decoder outputs computed at the end as one parallel GEMM over history.
// Precision (R10, validated): h fp16, weights fp16, single MMA term -> 4.5e-4.
// R12: persistent step kernel (one launch, flag sync). FAILED: 4-stage ring
//   with prefetch distance 4 -> cp.async overwrote the stage being consumed.
// R13: fix prefetch distance to 3 (written stage = cur+3 mod 4 != cur).
// ============================================================================

#define HSZ 1048576ull  // 1024*1024 elements per h snapshot

__device__ float   g_Wfused[3072u * 1024u];
__device__ __half  g_Wp[4096u * 1024u];
__device__ float   g_biasp[4096];
__device__ __half  g_Wd[256u * 1024u];
__device__ __half  g_hist[129ull * HSZ];
__device__ int     g_cnt[1024];          // [t][msub] producer counters (128x8)

// ---------------- helpers ----------------
__device__ __forceinline__ uint32_t smem_u32(const void* p) {
    uint32_t a;
    asm("{ .reg .u64 t; cvta.to.shared.u64 t, %1; cvt.u32.u64 %0, t; }" : "=r"(a) : "l"(p));
    return a;
}
__device__ __forceinline__ void cpasync16(uint32_t sa, const void* g) {
    asm volatile("cp.async.cg.shared.global [%0], [%1], 16;" :: "r"(sa), "l"(g));
}
#define CP_COMMIT() asm volatile("cp.async.commit_group;" ::: "memory")
#define CP_WAIT(n)  asm volatile("cp.async.wait_group %0;" :: "n"(n) : "memory")

__device__ __forceinline__ void ldsm4(uint32_t* r, uint32_t a) {
    asm volatile("ldmatrix.sync.aligned.m8n8.x4.shared.b16 {%0,%1,%2,%3}, [%4];"
                 : "=r"(r[0]), "=r"(r[1]), "=r"(r[2]), "=r"(r[3]) : "r"(a));
}
__device__ __forceinline__ void mma16816(float* c, const uint32_t* a,
                                         uint32_t b0, uint32_t b1) {
    asm volatile(
        "mma.sync.aligned.m16n8k16.row.col.f32.f16.f16.f32 "
        "{%0,%1,%2,%3}, {%4,%5,%6,%7}, {%8,%9}, {%0,%1,%2,%3};"
        : "+f"(c[0]), "+f"(c[1]), "+f"(c[2]), "+f"(c[3])
        : "r"(a[0]), "r"(a[1]), "r"(a[2]), "r"(a[3]), "r"(b0), "r"(b1));
}
__device__ __forceinline__ int ldacq(const int* p) {
    int v;
    asm volatile("ld.acquire.gpu.global.b32 %0, [%1];" : "=r"(v) : "l"(p) : "memory");
    return v;
}
__device__ __forceinline__ uint4 ldg_cg4(const void* p) {
    uint4 v;
    asm volatile("ld.global.cg.v4.u32 {%0,%1,%2,%3}, [%4];"
                 : "=r"(v.x), "=r"(v.y), "=r"(v.z), "=r"(v.w) : "l"(p));
    return v;
}

// Tile smem layout: 128 rows x 32 k (f16). Two rows share a 128B line;
// 16B groups permuted by line index -> conflict-free ldmatrix + cp.async.
__device__ __forceinline__ uint32_t toff(int r, int g) {
    int line = r >> 1;
    int p = (((r & 1) << 2) | g) ^ (line & 7);
    return (uint32_t)(line * 128 + p * 16);
}

// smem map: [0..512) bias | [1024, 1024+4*16384) stage ring | [66560, +33792) C
static constexpr unsigned OF_BUF = 1024u;
static constexpr unsigned STG    = 16384u;
static constexpr unsigned NSTG   = 4u;
static constexpr unsigned OF_C   = OF_BUF + NSTG * STG;            // 66560
static constexpr unsigned SMEM_BYTES = OF_C + 128u * 66u * 4u;     // 100352 -> occ 2

// ---------------- precompute kernels ----------------

// g_Wfused[3072,1024] = W_ih[3072,256] @ W_dec[256,1024], fp32 tiled
__global__ __launch_bounds__(256) void fuse_gemm(const float* __restrict__ A,
                                                 const float* __restrict__ B) {
    __shared__ __align__(16) float As[16][132];
    __shared__ __align__(16) float Bs[16][132];
    int tid = threadIdx.x;
    int tx = tid & 15, ty = tid >> 4;
    int m0 = blockIdx.y * 128, n0 = blockIdx.x * 128;
    float acc[8][8];
#pragma unroll
    for (int i = 0; i < 8; i++)
#pragma unroll
        for (int j = 0; j < 8; j++) acc[i][j] = 0.f;

    for (int k0 = 0; k0 < 256; k0 += 16) {
        for (int i = tid; i < 512; i += 256) {
            int row = i >> 2, kq = i & 3;
            float4 v = *(const float4*)(A + (size_t)(m0 + row) * 256 + k0 + kq * 4);
            As[kq * 4 + 0][row] = v.x; As[kq * 4 + 1][row] = v.y;
            As[kq * 4 + 2][row] = v.z; As[kq * 4 + 3][row] = v.w;
        }
        for (int i = tid; i < 512; i += 256) {
            int kk = i >> 5, nq = i & 31;
            *(float4*)&Bs[kk][nq * 4] =
                *(const float4*)(B + (size_t)(k0 + kk) * 1024 + n0 + nq * 4);
        }
        __syncthreads();
#pragma unroll
        for (int kk = 0; kk < 16; kk++) {
            float a[8], b[8];
#pragma unroll
            for (int i = 0; i < 8; i++) a[i] = As[kk][ty * 8 + i];
#pragma unroll
            for (int j = 0; j < 8; j++) b[j] = Bs[kk][tx * 8 + j];
#pragma unroll
            for (int i = 0; i < 8; i++)
#pragma unroll
                for (int j = 0; j < 8; j++) acc[i][j] += a[i] * b[j];
        }
        __syncthreads();
    }
#pragma unroll
    for (int i = 0; i < 8; i++)
#pragma unroll
        for (int j = 0; j < 8; j += 4) {
            float4 v = make_float4(acc[i][j], acc[i][j+1], acc[i][j+2], acc[i][j+3]);
            *(float4*)(g_Wfused + (size_t)(m0 + ty * 8 + i) * 1024 + n0 + tx * 8 + j) = v;
        }
}

__global__ void build_bias(const float* __restrict__ W_ih, const float* __restrict__ b_ih,
                           const float* __restrict__ b_hh, const float* __restrict__ b_dec) {
    int n = blockIdx.x * 256 + threadIdx.x;
    if (n >= 4096) return;
    int j = n >> 2, g = n & 3;
    float v;
    if (g == 3) {
        v = b_hh[2048 + j];
    } else {
        int row = g * 1024 + j;
        float dot = 0.f;
        for (int k = 0; k < 256; k++) dot += W_ih[(size_t)row * 256 + k] * b_dec[k];
        v = dot + b_ih[row];
        if (g < 2) v += b_hh[row];
    }
    g_biasp[n] = v;
}

__global__ void build_wp(const float* __restrict__ W_hh) {
    uint32_t idx = blockIdx.x * 256u + threadIdx.x;  // 4096*1024
    uint32_t n = idx >> 10, k = idx & 1023u;
    uint32_t j = n >> 2, g = n & 3u;
    float w;
    if (g == 0)      w = g_Wfused[(size_t)j * 1024 + k]          + W_hh[(size_t)j * 1024 + k];
    else if (g == 1) w = g_Wfused[(size_t)(1024 + j) * 1024 + k] + W_hh[(size_t)(1024 + j) * 1024 + k];
    else if (g == 2) w = g_Wfused[(size_t)(2048 + j) * 1024 + k];
    else             w = W_hh[(size_t)(2048 + j) * 1024 + k];
    g_Wp[idx] = __float2half_rn(w);
}

__global__ void split_wdec(const float* __restrict__ W_dec) {
    uint32_t idx = blockIdx.x * 256u + threadIdx.x;  // 262144
    g_Wd[idx] = __float2half_rn(W_dec[idx]);
}

__global__ void split_h0(const float* __restrict__ h0) {
    uint32_t idx = blockIdx.x * 256u + threadIdx.x;  // 1048576
    g_hist[idx] = __float2half_rn(h0[idx]);
}

__global__ void clear_cnt() { g_cnt[threadIdx.x] = 0; }

// ---------------- main GEMM kernel ----------------
// mode 0 (persistent steps): grid (8, 32). CTA (msub, nt) loops t = 0..127.
//   A = hist[t] (128 rows), B = Wp tile nt (128 gate cols), GRU -> hist[t+1].
//   Cross-step sync: cnt[t][msub] == 32 gates step t+1's A reads.
// mode 1 (decode): grid (8, 2, 128). slab = bz+1, out cols nt*128..+128.
__global__ __launch_bounds__(256, 2)
void gemm_kernel(int mode, const float* __restrict__ bias_ext,
                 float* __restrict__ outp) {
    extern __shared__ __align__(128) char smem[];
    float* bias = (float*)smem;
    float* Csm  = (float*)(smem + OF_C);
    const uint32_t sb = smem_u32(smem);
    const uint32_t sbuf = sb + OF_BUF;
    const int tid = threadIdx.x;

    const int msub = blockIdx.x;
    const int nt   = blockIdx.y;
    const int tdec = blockIdx.z;

    const char* Bp = (const char*)((mode == 0) ? (g_Wp + (size_t)nt * 131072)
                                               : (g_Wd + (size_t)nt * 131072));
    if (tid < 128)
        bias[tid] = (mode == 0) ? g_biasp[nt * 128 + tid] : bias_ext[nt * 128 + tid];

    const int w = tid >> 5, lane = tid & 31;
    const int wm = (w >> 2) * 64, wn = (w & 3) * 32;
    const int arow = (lane & 7) | (((lane >> 3) & 1) << 3);
    const int akg  = lane >> 4;
    const int brow = (lane & 7) | ((lane >> 4) << 3);
    const int bkg  = (lane >> 3) & 1;

    const int T0 = (mode == 0) ? 0 : tdec;
    const int T1 = T0 + ((mode == 0) ? 128 : 1);

    float c[4][4][4];

    for (int t = T0; t < T1; t++) {
        const int slab = (mode == 0) ? t : (tdec + 1);

        // ---- wait for h[t] to be fully written (persistent mode) ----
        if (mode == 0 && t > 0) {
            if (tid == 0) {
                const int* cp = &g_cnt[(t - 1) * 8 + msub];
                while (ldacq(cp) < 32) { }
            }
            __syncthreads();
        } else {
            __syncthreads();  // bias visible / Csm reuse ordering
        }

        const char* Ap = (const char*)(g_hist + (size_t)slab * HSZ + (size_t)msub * 131072);

        auto load_stage = [&](int ch, int s) {
            const uint32_t base = sbuf + (uint32_t)s * STG;
#pragma unroll
            for (int i = tid; i < 512; i += 256) {
                int r = i >> 2, g = i & 3;
                uint32_t so = toff(r, g);
                size_t go = (size_t)r * 2048 + (size_t)ch * 64 + (size_t)g * 16;
                cpasync16(base + so,        Ap + go);
                cpasync16(base + 8192 + so, Bp + go);
            }
        };

#pragma unroll
        for (int mi = 0; mi < 4; mi++)
#pragma unroll
            for (int ni = 0; ni < 4; ni++)
#pragma unroll
                for (int q = 0; q < 4; q++) c[mi][ni][q] = 0.f;

        // Prefetch distance 3 on a 4-stage ring: written stage is always
        // (cur + 3) mod 4 != cur. (R12 bug: distance 4 aliased cur.)
        load_stage(0, 0); CP_COMMIT();
        load_stage(1, 1); CP_COMMIT();
        load_stage(2, 2); CP_COMMIT();

        int s_cur = 0;
        for (int ck = 0; ck < 32; ck++) {
            CP_WAIT(2);
            __syncthreads();
            if (ck + 3 < 32) load_stage(ck + 3, (ck + 3) & 3);
            CP_COMMIT();

            const uint32_t base = sbuf + (uint32_t)s_cur * STG;
            const uint32_t sA = base, sB = base + 8192;
#pragma unroll
            for (int h = 0; h < 2; h++) {
                const int gA = h * 2 + akg, gB = h * 2 + bkg;
                uint32_t aF[4][4], bF[2][4];
#pragma unroll
                for (int mi = 0; mi < 4; mi++)
                    ldsm4(aF[mi], sA + toff(wm + mi * 16 + arow, gA));
#pragma unroll
                for (int nb = 0; nb < 2; nb++)
                    ldsm4(bF[nb], sB + toff(wn + nb * 16 + brow, gB));
#pragma unroll
                for (int mi = 0; mi < 4; mi++)
#pragma unroll
                    for (int ni = 0; ni < 4; ni++)
                        mma16816(c[mi][ni], aF[mi], bF[ni >> 1][(ni & 1) * 2],
                                 bF[ni >> 1][(ni & 1) * 2 + 1]);
            }
            s_cur = (s_cur + 1) & 3;
        }
        CP_WAIT(0);

        // ---- epilogue: two 64-col passes through dedicated C smem ----
#pragma unroll
        for (int p = 0; p < 2; p++) {
            if (((w & 3) >> 1) == p) {
                const int cr  = wm + (lane >> 2);
                const int ccl = ((w & 3) & 1) * 32 + 2 * (lane & 3);
#pragma unroll
                for (int mi = 0; mi < 4; mi++)
#pragma unroll
                    for (int ni = 0; ni < 4; ni++) {
                        float* q0 = Csm + (size_t)(cr + mi * 16) * 66 + ccl + ni * 8;
                        q0[0] = c[mi][ni][0]; q0[1] = c[mi][ni][1];
                        float* q1 = q0 + 8 * 66;
                        q1[0] = c[mi][ni][2]; q1[1] = c[mi][ni][3];
                    }
            }
            __syncthreads();

            const int r = tid >> 1, hc = tid & 1;
            const float* crow = Csm + (size_t)r * 66 + hc * 32;
            const int gc0 = p * 64 + hc * 32;  // local gate-col base (32 cols = 8 units)

            if (mode == 0) {
                const size_t rowoff = (size_t)(msub * 128 + r) * 1024 +
                                      (size_t)nt * 32 + p * 16 + hc * 8;
                uint4 pv = ldg_cg4(g_hist + (size_t)slab * HSZ + rowoff);
                const __half* ph = (const __half*)&pv;
                __align__(16) __half oh[8];
#pragma unroll
                for (int u = 0; u < 8; u++) {
                    float d0 = crow[4 * u + 0] + bias[gc0 + 4 * u + 0];
                    float d1 = crow[4 * u + 1] + bias[gc0 + 4 * u + 1];
                    float d2 = crow[4 * u + 2] + bias[gc0 + 4 * u + 2];
                    float d3 = crow[4 * u + 3] + bias[gc0 + 4 * u + 3];
                    float rr = 1.f / (1.f + __expf(-d0));
                    float zz = 1.f / (1.f + __expf(-d1));
                    float av = d2 + rr * d3;
                    float nn = 2.f / (1.f + __expf(-2.f * av)) - 1.f;  // tanh
                    float hp = __half2float(ph[u]);
                    float hv = nn + zz * (hp - nn);
                    oh[u] = __float2half_rn(hv);
                }
                *(uint4*)(g_hist + (size_t)(slab + 1) * HSZ + rowoff) = *(uint4*)oh;
            } else {
                float* op = outp + (size_t)(msub * 128 + r) * 32768 +
                            (size_t)tdec * 256 + (size_t)nt * 128 + gc0;
#pragma unroll
                for (int q = 0; q < 8; q++) {
                    float4 v;
                    v.x = crow[4 * q + 0] + bias[gc0 + 4 * q + 0];
                    v.y = crow[4 * q + 1] + bias[gc0 + 4 * q + 1];
                    v.z = crow[4 * q + 2] + bias[gc0 + 4 * q + 2];
                    v.w = crow[4 * q + 3] + bias[gc0 + 4 * q + 3];
                    *(float4*)(op + 4 * q) = v;
                }
            }
            __syncthreads();
        }

        // ---- publish h[t+1] (persistent mode) ----
        if (mode == 0) {
            __threadfence();
            __syncthreads();
            if (tid == 0) atomicAdd(&g_cnt[t * 8 + msub], 1);
        }
    }
}

// ---------------- launch ----------------
extern "C" void kernel_launch(void* const* d_in, const int* in_sizes, int n_in,
                              void* d_out, int out_size) {
    const float* h0   = (const float*)d_in[0];
    const float* Wih  = (const float*)d_in[1];
    const float* Whh  = (const float*)d_in[2];
    const float* bih  = (const float*)d_in[3];
    const float* bhh  = (const float*)d_in[4];
    const float* Wdec = (const float*)d_in[5];
    const float* bdec = (const float*)d_in[6];
    float* out = (float*)d_out;
    (void)in_sizes; (void)n_in; (void)out_size;

    cudaFuncSetAttribute((const void*)gemm_kernel,
                         cudaFuncAttributeMaxDynamicSharedMemorySize, SMEM_BYTES);

    fuse_gemm<<<dim3(8, 24), 256>>>(Wih, Wdec);
    build_bias<<<16, 256>>>(Wih, bih, bhh, bdec);
    build_wp<<<16384, 256>>>(Whh);
    split_wdec<<<1024, 256>>>(Wdec);
    split_h0<<<4096, 256>>>(h0);
    clear_cnt<<<1, 1024>>>();

    // persistent: all 128 GRU steps in one launch
    gemm_kernel<<<dim3(8, 32, 1), 256, SMEM_BYTES>>>(0, nullptr, nullptr);
    // decode: all 128 outputs in parallel
    gemm_kernel<<<dim3(8, 2, 128), 256, SMEM_BYTES>>>(1, bdec, out);
}

// round 17
// speedup vs baseline: 1.1250x; 1.1250x over previous
#include <cuda_runtime.h>
#include <cuda_bf16.h>
#include <cuda_fp16.h>
#include <cstdint>

// ============================================================================
// RecurrentDecoder: 128-step GRU (B=1024, H=1024) + Linear(1024->256).
// Decoder folded into recurrence: one GEMM/step  G = h @ Wp^T (+biasp),
//   Wp[4096,1024] gate-interleaved rows 4j+g, g in {r, z, i_n, h_n}.
//   r=sig(d0), z=sig(d1), n=tanh(d2 + r*d3), h' = n + z*(h - n)
// All decoder outputs computed at the end as one parallel GEMM over history.
// Precision (validated R10/R13): h fp16, weights fp16, single MMA term -> 4.5e-4.
// R15: 128x256 CTA tiles, 512 threads, occ 1, K-chunk 64, 4-stage 48KB ring
//   (prefetch distance 3 != ring size: no self-overwrite). Halves A-side L2
//   traffic (16 readers/slab, was 32) -> L2 no longer co-binding with tensor.
//   Per-step launches (persistence measured as a wash in R13).
// ============================================================================

#define HSZ 1048576ull  // 1024*1024 elements per h snapshot

__device__ float   g_Wfused[3072u * 1024u];
__device__ __half  g_Wp[4096u * 1024u];
__device__ float   g_biasp[4096];
__device__ __half  g_Wd[256u * 1024u];
__device__ __half  g_hist[129ull * HSZ];

// ---------------- helpers ----------------
__device__ __forceinline__ uint32_t smem_u32(const void* p) {
    uint32_t a;
    asm("{ .reg .u64 t; cvta.to.shared.u64 t, %1; cvt.u32.u64 %0, t; }" : "=r"(a) : "l"(p));
    return a;
}
__device__ __forceinline__ void cpasync16(uint32_t sa, const void* g) {
    asm volatile("cp.async.cg.shared.global [%0], [%1], 16;" :: "r"(sa), "l"(g));
}
#define CP_COMMIT() asm volatile("cp.async.commit_group;" ::: "memory")
#define CP_WAIT(n)  asm volatile("cp.async.wait_group %0;" :: "n"(n) : "memory")

__device__ __forceinline__ void ldsm4(uint32_t* r, uint32_t a) {
    asm volatile("ldmatrix.sync.aligned.m8n8.x4.shared.b16 {%0,%1,%2,%3}, [%4];"
                 : "=r"(r[0]), "=r"(r[1]), "=r"(r[2]), "=r"(r[3]) : "r"(a));
}
__device__ __forceinline__ void mma16816(float* c, const uint32_t* a,
                                         uint32_t b0, uint32_t b1) {
    asm volatile(
        "mma.sync.aligned.m16n8k16.row.col.f32.f16.f16.f32 "
        "{%0,%1,%2,%3}, {%4,%5,%6,%7}, {%8,%9}, {%0,%1,%2,%3};"
        : "+f"(c[0]), "+f"(c[1]), "+f"(c[2]), "+f"(c[3])
        : "r"(a[0]), "r"(a[1]), "r"(a[2]), "r"(a[3]), "r"(b0), "r"(b1));
}

// Tile smem layout: rows x 64 k (f16) = 128B per row = one 128B line per row.
// 16B groups XOR-permuted by row -> conflict-free cp.async stores + ldmatrix.
__device__ __forceinline__ uint32_t toff(int r, int g) {
    return (uint32_t)(r * 128 + ((g ^ (r & 7)) << 4));
}

// smem map: [0..1024) bias (256 f32) | [1024..) 4 stages x 48KB (A 16K | B 32K)
// Epilogue reuses ring as C tile [128][264] f32 (135168 B <= 192KB ring).
static constexpr unsigned OF_BUF = 1024u;
static constexpr unsigned STG    = 49152u;
static constexpr unsigned NSTG   = 4u;
static constexpr unsigned SMEM_BYTES = OF_BUF + NSTG * STG;  // 197632 (occ 1)

// ---------------- precompute kernels ----------------

// g_Wfused[3072,1024] = W_ih[3072,256] @ W_dec[256,1024], fp32 tiled
__global__ __launch_bounds__(256) void fuse_gemm(const float* __restrict__ A,
                                                 const float* __restrict__ B) {
    __shared__ __align__(16) float As[16][132];
    __shared__ __align__(16) float Bs[16][132];
    int tid = threadIdx.x;
    int tx = tid & 15, ty = tid >> 4;
    int m0 = blockIdx.y * 128, n0 = blockIdx.x * 128;
    float acc[8][8];
#pragma unroll
    for (int i = 0; i < 8; i++)
#pragma unroll
        for (int j = 0; j < 8; j++) acc[i][j] = 0.f;

    for (int k0 = 0; k0 < 256; k0 += 16) {
        for (int i = tid; i < 512; i += 256) {
            int row = i >> 2, kq = i & 3;
            float4 v = *(const float4*)(A + (size_t)(m0 + row) * 256 + k0 + kq * 4);
            As[kq * 4 + 0][row] = v.x; As[kq * 4 + 1][row] = v.y;
            As[kq * 4 + 2][row] = v.z; As[kq * 4 + 3][row] = v.w;
        }
        for (int i = tid; i < 512; i += 256) {
            int kk = i >> 5, nq = i & 31;
            *(float4*)&Bs[kk][nq * 4] =
                *(const float4*)(B + (size_t)(k0 + kk) * 1024 + n0 + nq * 4);
        }
        __syncthreads();
#pragma unroll
        for (int kk = 0; kk < 16; kk++) {
            float a[8], b[8];
#pragma unroll
            for (int i = 0; i < 8; i++) a[i] = As[kk][ty * 8 + i];
#pragma unroll
            for (int j = 0; j < 8; j++) b[j] = Bs[kk][tx * 8 + j];
#pragma unroll
            for (int i = 0; i < 8; i++)
#pragma unroll
                for (int j = 0; j < 8; j++) acc[i][j] += a[i] * b[j];
        }
        __syncthreads();
    }
#pragma unroll
    for (int i = 0; i < 8; i++)
#pragma unroll
        for (int j = 0; j < 8; j += 4) {
            float4 v = make_float4(acc[i][j], acc[i][j+1], acc[i][j+2], acc[i][j+3]);
            *(float4*)(g_Wfused + (size_t)(m0 + ty * 8 + i) * 1024 + n0 + tx * 8 + j) = v;
        }
}

__global__ void build_bias(const float* __restrict__ W_ih, const float* __restrict__ b_ih,
                           const float* __restrict__ b_hh, const float* __restrict__ b_dec) {
    int n = blockIdx.x * 256 + threadIdx.x;
    if (n >= 4096) return;
    int j = n >> 2, g = n & 3;
    float v;
    if (g == 3) {
        v = b_hh[2048 + j];
    } else {
        int row = g * 1024 + j;
        float dot = 0.f;
        for (int k = 0; k < 256; k++) dot += W_ih[(size_t)row * 256 + k] * b_dec[k];
        v = dot + b_ih[row];
        if (g < 2) v += b_hh[row];
    }
    g_biasp[n] = v;
}

__global__ void build_wp(const float* __restrict__ W_hh) {
    uint32_t idx = blockIdx.x * 256u + threadIdx.x;  // 4096*1024
    uint32_t n = idx >> 10, k = idx & 1023u;
    uint32_t j = n >> 2, g = n & 3u;
    float w;
    if (g == 0)      w = g_Wfused[(size_t)j * 1024 + k]          + W_hh[(size_t)j * 1024 + k];
    else if (g == 1) w = g_Wfused[(size_t)(1024 + j) * 1024 + k] + W_hh[(size_t)(1024 + j) * 1024 + k];
    else if (g == 2) w = g_Wfused[(size_t)(2048 + j) * 1024 + k];
    else             w = W_hh[(size_t)(2048 + j) * 1024 + k];
    g_Wp[idx] = __float2half_rn(w);
}

__global__ void split_wdec(const float* __restrict__ W_dec) {
    uint32_t idx = blockIdx.x * 256u + threadIdx.x;  // 262144
    g_Wd[idx] = __float2half_rn(W_dec[idx]);
}

__global__ void split_h0(const float* __restrict__ h0) {
    uint32_t idx = blockIdx.x * 256u + threadIdx.x;  // 1048576
    g_hist[idx] = __float2half_rn(h0[idx]);
}

// ---------------- main GEMM kernel ----------------
// Tile 128(M) x 256(N), 512 threads, 16 warps as 2m x 8n of 64x32 warp tiles.
// mode 0 (step t): grid (8, 16). msub = bx (128 batch rows), nt = by (256
//   gate cols = 64 units). A = hist[t]; B = Wp rows [nt*256, +256).
//   GRU epilogue -> hist[t+1].
// mode 1 (decode): grid (8, 1, 128). slab = bz+1, B = W_dec (all 256 rows),
//   out[b, bz, :] = C + b_dec.
__global__ __launch_bounds__(512, 1)
void gemm_kernel(int mode, int t, const float* __restrict__ bias_ext,
                 float* __restrict__ outp) {
    extern __shared__ __align__(128) char smem[];
    float* bias = (float*)smem;
    const uint32_t sb = smem_u32(smem);
    const uint32_t sbuf = sb + OF_BUF;
    const int tid = threadIdx.x;

    const int msub = blockIdx.x;
    const int nt   = blockIdx.y;
    const int tdec = blockIdx.z;
    const int slab = (mode == 0) ? t : (tdec + 1);

    const char* Ap = (const char*)(g_hist + (size_t)slab * HSZ + (size_t)msub * 131072);
    const char* Bp = (const char*)((mode == 0) ? (g_Wp + (size_t)nt * 262144) : g_Wd);

    if (tid < 256)
        bias[tid] = (mode == 0) ? g_biasp[nt * 256 + tid] : bias_ext[tid];

    // ---- load one k-chunk (64 k) into stage s: A 16KB | B 32KB ----
    auto load_stage = [&](int ch, int s) {
        const uint32_t base = sbuf + (uint32_t)s * STG;
#pragma unroll
        for (int i = tid; i < 1024; i += 512) {
            int r = i >> 3, g = i & 7;
            cpasync16(base + toff(r, g),
                      Ap + (size_t)r * 2048 + (size_t)ch * 128 + (size_t)g * 16);
        }
#pragma unroll
        for (int i = tid; i < 2048; i += 512) {
            int r = i >> 3, g = i & 7;
            cpasync16(base + 16384 + toff(r, g),
                      Bp + (size_t)r * 2048 + (size_t)ch * 128 + (size_t)g * 16);
        }
    };

    const int w = tid >> 5, lane = tid & 31;
    const int wm = (w >> 3) * 64, wn = (w & 7) * 32;
    const int arow = (lane & 7) | (((lane >> 3) & 1) << 3);
    const int akg  = lane >> 4;
    const int brow = (lane & 7) | ((lane >> 4) << 3);
    const int bkg  = (lane >> 3) & 1;

    float c[4][4][4];
#pragma unroll
    for (int mi = 0; mi < 4; mi++)
#pragma unroll
        for (int ni = 0; ni < 4; ni++)
#pragma unroll
            for (int q = 0; q < 4; q++) c[mi][ni][q] = 0.f;

    // Prefetch distance 3 on a 4-stage ring: written stage (ck+3)&3 != ck&3.
    load_stage(0, 0); CP_COMMIT();
    load_stage(1, 1); CP_COMMIT();
    load_stage(2, 2); CP_COMMIT();

    for (int ck = 0; ck < 16; ck++) {
        CP_WAIT(2);
        __syncthreads();
        if (ck + 3 < 16) load_stage(ck + 3, (ck + 3) & 3);
        CP_COMMIT();

        const uint32_t base = sbuf + (uint32_t)(ck & 3) * STG;
        const uint32_t sA = base, sB = base + 16384;
#pragma unroll
        for (int ks = 0; ks < 4; ks++) {
            const int gA = ks * 2 + akg, gB = ks * 2 + bkg;
            uint32_t aF[4][4], bF[2][4];
#pragma unroll
            for (int mi = 0; mi < 4; mi++)
                ldsm4(aF[mi], sA + toff(wm + mi * 16 + arow, gA));
#pragma unroll
            for (int nb = 0; nb < 2; nb++)
                ldsm4(bF[nb], sB + toff(wn + nb * 16 + brow, gB));
#pragma unroll
            for (int mi = 0; mi < 4; mi++)
#pragma unroll
                for (int ni = 0; ni < 4; ni++)
                    mma16816(c[mi][ni], aF[mi], bF[ni >> 1][(ni & 1) * 2],
                             bF[ni >> 1][(ni & 1) * 2 + 1]);
        }
    }
    CP_WAIT(0);
    __syncthreads();  // all reads of the ring done before C overwrites it

    // ---- C -> smem [128][264] f32 (reuses stage ring) ----
    float* Csm = (float*)(smem + OF_BUF);
    {
        const int cr = wm + (lane >> 2);
        const int cc = wn + 2 * (lane & 3);
#pragma unroll
        for (int mi = 0; mi < 4; mi++)
#pragma unroll
            for (int ni = 0; ni < 4; ni++) {
                float* p = Csm + (size_t)(cr + mi * 16) * 264 + cc + ni * 8;
                p[0] = c[mi][ni][0]; p[1] = c[mi][ni][1];
                float* q = p + 8 * 264;
                q[0] = c[mi][ni][2]; q[1] = c[mi][ni][3];
            }
    }
    __syncthreads();

    const int r = tid >> 2, q4 = tid & 3;          // 4 threads/row, 64 cols each
    const float* crow = Csm + (size_t)r * 264 + q4 * 64;
    const float* bl = bias + q4 * 64;

    if (mode == 0) {
        // GRU epilogue: 16 units (64 gate cols) per thread
        const size_t rowoff = (size_t)(msub * 128 + r) * 1024 + (size_t)nt * 64 + q4 * 16;
        const __half* php = g_hist + (size_t)slab * HSZ + rowoff;
        __align__(16) __half ph[16], oh[16];
        *(uint4*)(ph)     = *(const uint4*)(php);
        *(uint4*)(ph + 8) = *(const uint4*)(php + 8);
#pragma unroll
        for (int u = 0; u < 16; u++) {
            float d0 = crow[4 * u + 0] + bl[4 * u + 0];
            float d1 = crow[4 * u + 1] + bl[4 * u + 1];
            float d2 = crow[4 * u + 2] + bl[4 * u + 2];
            float d3 = crow[4 * u + 3] + bl[4 * u + 3];
            float rr = 1.f / (1.f + __expf(-d0));
            float zz = 1.f / (1.f + __expf(-d1));
            float av = d2 + rr * d3;
            float nn = 2.f / (1.f + __expf(-2.f * av)) - 1.f;  // tanh
            float hp = __half2float(ph[u]);
            float hv = nn + zz * (hp - nn);
            oh[u] = __float2half_rn(hv);
        }
        __half* nhp = g_hist + (size_t)(slab + 1) * HSZ + rowoff;
        *(uint4*)(nhp)     = *(uint4*)(oh);
        *(uint4*)(nhp + 8) = *(uint4*)(oh + 8);
    } else {
        // decode epilogue: out[b, t, :] = C + b_dec
        float* op = outp + (size_t)(msub * 128 + r) * 32768 + (size_t)tdec * 256 + q4 * 64;
#pragma unroll
        for (int u = 0; u < 16; u++) {
            float4 v;
            v.x = crow[4 * u + 0] + bl[4 * u + 0];
            v.y = crow[4 * u + 1] + bl[4 * u + 1];
            v.z = crow[4 * u + 2] + bl[4 * u + 2];
            v.w = crow[4 * u + 3] + bl[4 * u + 3];
            *(float4*)(op + 4 * u) = v;
        }
    }
}

// ---------------- launch ----------------
extern "C" void kernel_launch(void* const* d_in, const int* in_sizes, int n_in,
                              void* d_out, int out_size) {
    const float* h0   = (const float*)d_in[0];
    const float* Wih  = (const float*)d_in[1];
    const float* Whh  = (const float*)d_in[2];
    const float* bih  = (const float*)d_in[3];
    const float* bhh  = (const float*)d_in[4];
    const float* Wdec = (const float*)d_in[5];
    const float* bdec = (const float*)d_in[6];
    float* out = (float*)d_out;
    (void)in_sizes; (void)n_in; (void)out_size;

    cudaFuncSetAttribute((const void*)gemm_kernel,
                         cudaFuncAttributeMaxDynamicSharedMemorySize, SMEM_BYTES);

    fuse_gemm<<<dim3(8, 24), 256>>>(Wih, Wdec);
    build_bias<<<16, 256>>>(Wih, bih, bhh, bdec);
    build_wp<<<16384, 256>>>(Whh);
    split_wdec<<<1024, 256>>>(Wdec);
    split_h0<<<4096, 256>>>(h0);

    for (int t = 0; t < 128; t++)
        gemm_kernel<<<dim3(8, 16, 1), 512, SMEM_BYTES>>>(0, t, nullptr, nullptr);

    gemm_kernel<<<dim3(8, 1, 128), 512, SMEM_BYTES>>>(1, 0, bdec, out);
}